// round 5
// baseline (speedup 1.0000x reference)
#include <cuda_runtime.h>
#include <cuda_fp16.h>
#include <cstdint>

// ---------------------------------------------------------------------------
// QuantizerEncoder via mma.sync m16n8k16 fp16 (2-way split, 3 passes).
//
//   score[code][px] = sum_d Mmat[code][d] * x[d][px]
//   Mmat[k][d] = sum_c wq[c][d]*keys[k][c];  keys[k][c] = sum_d cb[k][d]*wk[c][d]
//   out[n,h,w,m] = argmax_code score  (written as float)
//
// A: prebuilt in global in m16n8k16 per-thread frag layout (fp16 hi/lo), L2-res
// B: per-CTA smem, frag-linear fp16 pairs, hi/lo (64KB) -> 2 CTAs/SM
// ---------------------------------------------------------------------------

typedef unsigned long long ULL;

__device__ float g_keys[4 * 256 * 128];   // [m][k][c]
__device__ __half g_A[262144];            // frag layout, 512KB

static __device__ __forceinline__ void mma16(float* d, uint4 a, uint2 b) {
    asm volatile(
        "mma.sync.aligned.m16n8k16.row.col.f32.f16.f16.f32 "
        "{%0,%1,%2,%3}, {%4,%5,%6,%7}, {%8,%9}, {%0,%1,%2,%3};"
        : "+f"(d[0]), "+f"(d[1]), "+f"(d[2]), "+f"(d[3])
        : "r"(a.x), "r"(a.y), "r"(a.z), "r"(a.w), "r"(b.x), "r"(b.y));
}

// A-frag half index for (m, k(code), d, split)
static __device__ __forceinline__ int a_index(int m, int k, int d, int split) {
    int half_ = k >> 7, w = (k & 127) >> 4, r16 = k & 15;
    int ks = d >> 4, kd = d & 15;
    int reg = ((r16 >> 3) & 1) + ((kd >> 3) & 1) * 2;
    int ln = (r16 & 7) * 4 + ((kd >> 1) & 3);
    int h = kd & 1;
    return ((((((m * 2 + half_) * 8 + w) * 8 + ks) * 2 + split) * 32 + ln) * 4 + reg) * 2 + h;
}

// ---------------- setup 1: keys[m][k][c] = sum_d cb[m][k][d]*wk[m][c][d] ----
__global__ __launch_bounds__(256, 1)
void keys_kernel(const float* __restrict__ cb, const float* __restrict__ wk) {
    extern __shared__ float sm[];
    float* swkT = sm;            // [128 d][129]
    float* scb = sm + 129 * 128; // [8 k][128 d]
    const int m = blockIdx.y, kch = blockIdx.x, t = threadIdx.x;

    const float4* wk4 = (const float4*)(wk + (size_t)m * 16384);
#pragma unroll
    for (int i = 0; i < 16; i++) {
        int j = i * 256 + t, c = j >> 5, d4 = j & 31;
        float4 v = __ldg(wk4 + j);
        swkT[(4 * d4 + 0) * 129 + c] = v.x;
        swkT[(4 * d4 + 1) * 129 + c] = v.y;
        swkT[(4 * d4 + 2) * 129 + c] = v.z;
        swkT[(4 * d4 + 3) * 129 + c] = v.w;
    }
    ((float4*)scb)[t] = __ldg((const float4*)(cb + ((size_t)m * 256 + kch * 8) * 128) + t);
    __syncthreads();
#pragma unroll
    for (int i = 0; i < 4; i++) {
        int o = i * 256 + t, kl = o >> 7, c = o & 127;
        float s = 0.f;
#pragma unroll 8
        for (int d = 0; d < 128; d++) s += scb[kl * 128 + d] * swkT[d * 129 + c];
        g_keys[((size_t)m * 256 + kch * 8 + kl) * 128 + c] = s;
    }
}

// ---------------- setup 2: Mmat -> fp16 hi/lo in HMMA frag layout -----------
__global__ __launch_bounds__(256, 1)
void mmat_kernel(const float* __restrict__ wq) {
    extern __shared__ float sm[];
    float* swq = sm;             // [128 c][128 d]
    float* skeys = sm + 16384;   // [8 k][128 c]
    const int m = blockIdx.y, kch = blockIdx.x, t = threadIdx.x;

    const float4* wq4 = (const float4*)(wq + (size_t)m * 16384);
#pragma unroll
    for (int i = 0; i < 16; i++) ((float4*)swq)[i * 256 + t] = __ldg(wq4 + i * 256 + t);
    ((float4*)skeys)[t] =
        ((const float4*)(g_keys + ((size_t)m * 256 + kch * 8) * 128))[t];
    __syncthreads();
#pragma unroll
    for (int i = 0; i < 4; i++) {
        int o = i * 256 + t, kl = o >> 7, d = o & 127;
        float val = 0.f;
#pragma unroll 8
        for (int c = 0; c < 128; c++) val += swq[c * 128 + d] * skeys[kl * 128 + c];
        __half hi = __float2half_rn(val);
        __half lo = __float2half_rn(val - __half2float(hi));
        int k = kch * 8 + kl;
        g_A[a_index(m, k, d, 0)] = hi;
        g_A[a_index(m, k, d, 1)] = lo;
    }
}

// ---------------- main: fp16-split HMMA score + fused argmax ----------------
// CTA: 256 threads, 128 px, one m. grid = (512, 4). 2 CTAs/SM.
// smem: B hi (8192 b32 = 32KB) + B lo (32KB) + keys ULL[16*128] (16KB) = 80KB
// B slot (b32): ((j*8+ks)*32 + lane)*2 + r,
//   where j=px>>3, ks=d>>4, lane=(px&7)*4+((d>>1)&3), r=(d>>3)&1; pair (d even, d+1)
__global__ __launch_bounds__(256, 2)
void score_kernel(const float* __restrict__ latent, float* __restrict__ out) {
    extern __shared__ unsigned sbB[];
    ULL* keys = (ULL*)(sbB + 16384);

    const int t = threadIdx.x, lane = t & 31, wid = t >> 5;
    const int m = blockIdx.y;
    const int n = blockIdx.x >> 5;
    const int p0 = (blockIdx.x & 31) << 7;

    // ---- convert latent [128 d][128 px] -> fp16 hi/lo frag-linear smem ----
    const float* xb = latent + ((size_t)(n * 512 + m * 128)) * 4096 + p0;
#pragma unroll
    for (int i = 0; i < 8; i++) {
        int item = i * 256 + t;
        int dp = item >> 5, p4 = item & 31;          // d = 2*dp
        float4 v0 = __ldg((const float4*)(xb + (size_t)(2 * dp) * 4096) + p4);
        float4 v1 = __ldg((const float4*)(xb + (size_t)(2 * dp + 1) * 4096) + p4);
        int ks = dp >> 3, l4 = dp & 3, r = (dp >> 2) & 1;
        float e0[4] = {v0.x, v0.y, v0.z, v0.w};
        float e1[4] = {v1.x, v1.y, v1.z, v1.w};
#pragma unroll
        for (int q = 0; q < 4; q++) {
            int px = p4 * 4 + q;
            int j = px >> 3, lb = (px & 7) * 4 + l4;
            int slot = ((j * 8 + ks) * 32 + lb) * 2 + r;
            __half h0 = __float2half_rn(e0[q]);
            __half h1 = __float2half_rn(e1[q]);
            __half g0 = __float2half_rn(e0[q] - __half2float(h0));
            __half g1 = __float2half_rn(e1[q] - __half2float(h1));
            sbB[slot] = ((unsigned)__half_as_ushort(h1) << 16) | __half_as_ushort(h0);
            sbB[8192 + slot] = ((unsigned)__half_as_ushort(g1) << 16) | __half_as_ushort(g0);
        }
    }
    __syncthreads();

    for (int half_ = 0; half_ < 2; half_++) {
        float acc[16][4];
#pragma unroll
        for (int j = 0; j < 16; j++)
#pragma unroll
            for (int c = 0; c < 4; c++) acc[j][c] = 0.f;

        const uint4* pA = ((const uint4*)g_A) + (size_t)((m * 2 + half_) * 8 + wid) * 512;

#pragma unroll
        for (int ks = 0; ks < 8; ks++) {
            uint4 ah = __ldg(pA + (ks * 2 + 0) * 32 + lane);
            uint4 al = __ldg(pA + (ks * 2 + 1) * 32 + lane);
#pragma unroll 4
            for (int j = 0; j < 16; j++) {
                int f = ((j * 8 + ks) * 32 + lane) * 2;
                uint2 bh = *(const uint2*)(sbB + f);
                uint2 bl = *(const uint2*)(sbB + 8192 + f);
                mma16(acc[j], ah, bh);
                mma16(acc[j], ah, bl);
                mma16(acc[j], al, bh);
            }
        }

        // ---- fused argmax over this warp's 16 codes ----
        int r0 = half_ * 128 + wid * 16 + (lane >> 2);
#pragma unroll
        for (int j = 0; j < 16; j++) {
#pragma unroll
            for (int cc = 0; cc < 2; cc++) {
                float v0 = acc[j][cc];       // code r0
                float v1 = acc[j][2 + cc];   // code r0+8
                float bv; int bc;
                if (v1 > v0) { bv = v1; bc = r0 + 8; } else { bv = v0; bc = r0; }
                unsigned ub = __float_as_uint(bv);
                ub = (ub & 0x80000000u) ? ~ub : (ub | 0x80000000u);
                ULL key = ((ULL)ub << 32) | (unsigned)(255 - bc);
#pragma unroll
                for (int o = 4; o <= 16; o <<= 1) {
                    ULL other = __shfl_xor_sync(0xffffffffu, key, o);
                    if (other > key) key = other;
                }
                if (lane < 4) {
                    int px = j * 8 + (lane & 3) * 2 + cc;
                    keys[(half_ * 8 + wid) * 128 + px] = key;
                }
            }
        }
    }
    __syncthreads();

    if (t < 128) {
        ULL best = keys[t];
#pragma unroll
        for (int g = 1; g < 16; g++) {
            ULL o = keys[g * 128 + t];
            if (o > best) best = o;
        }
        int code = 255 - (int)(best & 0xFF);
        int pix = n * 4096 + p0 + t;
        out[pix * 4 + m] = (float)code;
    }
}

extern "C" void kernel_launch(void* const* d_in, const int* in_sizes, int n_in,
                              void* d_out, int out_size) {
    const float* latent = (const float*)d_in[0];
    const float* cb     = (const float*)d_in[1];
    const float* wq     = (const float*)d_in[2];
    const float* wk     = (const float*)d_in[3];

    cudaFuncSetAttribute(keys_kernel, cudaFuncAttributeMaxDynamicSharedMemorySize, 70144);
    cudaFuncSetAttribute(mmat_kernel, cudaFuncAttributeMaxDynamicSharedMemorySize, 69632);
    cudaFuncSetAttribute(score_kernel, cudaFuncAttributeMaxDynamicSharedMemorySize, 81920);

    keys_kernel<<<dim3(32, 4), 256, 70144>>>(cb, wk);
    mmat_kernel<<<dim3(32, 4), 256, 69632>>>(wq);
    score_kernel<<<dim3(512, 4), 256, 81920>>>(latent, (float*)d_out);
}